// round 1
// baseline (speedup 1.0000x reference)
#include <cuda_runtime.h>

// Problem shape (fixed by the reference)
#define BB 16
#define SS 4096
#define CC 512
#define ROWS_PER_BLOCK 8
#define BLOCKS_PER_BATCH (SS / ROWS_PER_BLOCK)   // 512
#define NBLOCKS (BB * BLOCKS_PER_BATCH)          // 8192
#define NTHREADS 128                             // 128 thr * float4 = 512 cols

// Scratch: every element written unconditionally every launch -> no init kernel,
// fully deterministic (no float atomics anywhere).
__device__ float g_partial_loss[NBLOCKS];
__device__ float g_partial_cnt[NBLOCKS];
__device__ float g_batch_loss[BB];
__device__ float g_batch_cnt[BB];

__global__ __launch_bounds__(NTHREADS) void row_loss_kernel(
    const float* __restrict__ logits,
    const float* __restrict__ target,
    const int*   __restrict__ mask)
{
    const int blk  = blockIdx.x;
    const int b    = blk / BLOCKS_PER_BATCH;
    const int s0   = (blk % BLOCKS_PER_BATCH) * ROWS_PER_BLOCK;
    const int t    = threadIdx.x;
    const int lane = t & 31;
    const int wid  = t >> 5;

    __shared__ int   smask[ROWS_PER_BLOCK];
    __shared__ float sm[4];      // per-warp max
    __shared__ float s3[12];     // per-warp {e, dot, st}

    if (t < ROWS_PER_BLOCK) smask[t] = mask[b * SS + s0 + t];
    __syncthreads();

    float loss_acc = 0.f;
    float cnt_acc  = 0.f;

    #pragma unroll
    for (int r = 0; r < ROWS_PER_BLOCK; ++r) {
        if (smask[r] != 1) continue;   // uniform branch: skip ALL HBM traffic for masked rows

        const size_t row = (size_t)(b * SS + s0 + r);
        const float4 lv = ((const float4*)logits)[row * (CC / 4) + t];
        const float4 tv = ((const float4*)target)[row * (CC / 4) + t];

        // --- row max (broadcast to all threads) ---
        float m = fmaxf(fmaxf(lv.x, lv.y), fmaxf(lv.z, lv.w));
        #pragma unroll
        for (int o = 16; o; o >>= 1) m = fmaxf(m, __shfl_xor_sync(0xffffffffu, m, o));
        if (lane == 0) sm[wid] = m;
        __syncthreads();
        m = fmaxf(fmaxf(sm[0], sm[1]), fmaxf(sm[2], sm[3]));

        // --- sumexp / dot(target,logits) / sum(target), reduced to thread 0 ---
        float e   = __expf(lv.x - m) + __expf(lv.y - m) + __expf(lv.z - m) + __expf(lv.w - m);
        float dot = lv.x * tv.x + lv.y * tv.y + lv.z * tv.z + lv.w * tv.w;
        float st  = tv.x + tv.y + tv.z + tv.w;
        #pragma unroll
        for (int o = 16; o; o >>= 1) {
            e   += __shfl_xor_sync(0xffffffffu, e, o);
            dot += __shfl_xor_sync(0xffffffffu, dot, o);
            st  += __shfl_xor_sync(0xffffffffu, st, o);
        }
        if (lane == 0) { s3[wid * 3] = e; s3[wid * 3 + 1] = dot; s3[wid * 3 + 2] = st; }
        __syncthreads();
        if (t == 0) {
            float es = s3[0] + s3[3] + s3[6] + s3[9];
            float ds = s3[1] + s3[4] + s3[7] + s3[10];
            float ss = s3[2] + s3[5] + s3[8] + s3[11];
            loss_acc += (m + __logf(es)) * ss - ds;
            cnt_acc  += 1.f;
        }
    }

    if (t == 0) {
        g_partial_loss[blk] = loss_acc;
        g_partial_cnt[blk]  = cnt_acc;
    }
}

__global__ __launch_bounds__(512) void batch_reduce_kernel()
{
    const int b = blockIdx.x;
    const int t = threadIdx.x;
    __shared__ float sl[512];
    __shared__ float sc[512];
    sl[t] = g_partial_loss[b * BLOCKS_PER_BATCH + t];
    sc[t] = g_partial_cnt[b * BLOCKS_PER_BATCH + t];
    __syncthreads();
    #pragma unroll
    for (int o = 256; o >= 1; o >>= 1) {
        if (t < o) { sl[t] += sl[t + o]; sc[t] += sc[t + o]; }
        __syncthreads();
    }
    if (t == 0) { g_batch_loss[b] = sl[0]; g_batch_cnt[b] = sc[0]; }
}

__global__ void finalize_kernel(float* __restrict__ out)
{
    const int t = threadIdx.x;
    float pb = 0.f, has = 0.f;
    if (t < BB) {
        float c = g_batch_cnt[t];
        float s = g_batch_loss[t];
        has = (c > 0.f) ? 1.f : 0.f;
        pb  = (s / fmaxf(c, 1.f)) * has;
    }
    #pragma unroll
    for (int o = 16; o; o >>= 1) {
        pb  += __shfl_xor_sync(0xffffffffu, pb, o);
        has += __shfl_xor_sync(0xffffffffu, has, o);
    }
    if (t == 0) out[0] = pb / fmaxf(has, 1.f);
}

extern "C" void kernel_launch(void* const* d_in, const int* in_sizes, int n_in,
                              void* d_out, int out_size)
{
    const float* logits = (const float*)d_in[0];
    const float* target = (const float*)d_in[1];
    const int*   mask   = (const int*)d_in[2];
    float*       out    = (float*)d_out;

    row_loss_kernel<<<NBLOCKS, NTHREADS>>>(logits, target, mask);
    batch_reduce_kernel<<<BB, 512>>>();
    finalize_kernel<<<1, 32>>>(out);
}